// round 1
// baseline (speedup 1.0000x reference)
#include <cuda_runtime.h>
#include <cuda_bf16.h>
#include <cstdint>

// Problem constants: B=16, C1=C2=64, H=W=160, E=4, K=3, R=4
#define NB   16
#define NC   64
#define NH   160
#define NW   160
#define NE   4
#define NR   4
#define HW   (NH*NW)          // 25600
#define BN_EPS 1e-5f

// ---------------- device scratch (no allocations allowed) ----------------
__device__ float g_pooled[NB*NC];            // [b][c]
__device__ float g_attn[NB*NE];              // [b][e]
__device__ float g_scale[NC];                // BN scale
__device__ float g_shift[NC];                // BN shift
__device__ float g_wcomb[NB*NC*9*NC];        // [b][c1][kk][c2]  (2.36 MB)

// ---------------- 1) global average pool:  pooled[b][c] = mean(x[b][c]) ----------------
__global__ void pool_k(const float* __restrict__ x) {
    const int bc = blockIdx.x;                       // 0..1023
    const float4* p4 = (const float4*)(x + (size_t)bc * HW);
    float s = 0.f;
    for (int i = threadIdx.x; i < HW/4; i += 256) {  // 25 iters
        float4 v = p4[i];
        s += (v.x + v.y) + (v.z + v.w);
    }
    // warp reduce
    #pragma unroll
    for (int o = 16; o > 0; o >>= 1) s += __shfl_down_sync(~0u, s, o);
    __shared__ float sm[8];
    if ((threadIdx.x & 31) == 0) sm[threadIdx.x >> 5] = s;
    __syncthreads();
    if (threadIdx.x < 8) {
        float v = sm[threadIdx.x];
        v += __shfl_down_sync(0xffu, v, 4);
        v += __shfl_down_sync(0xffu, v, 2);
        v += __shfl_down_sync(0xffu, v, 1);
        if (threadIdx.x == 0) g_pooled[bc] = v * (1.f / (float)HW);
    }
}

// ---------------- 2) attention MLP + softmax + BN constants (1 block, 64 thr) ----------------
__global__ void attn_k(const float* __restrict__ w1,   // [R][C1]
                       const float* __restrict__ w2,   // [E][R]
                       const float* __restrict__ gamma,
                       const float* __restrict__ beta,
                       const float* __restrict__ mean,
                       const float* __restrict__ var) {
    __shared__ float hs[NB*NR];
    __shared__ float ls[NB*NE];
    const int t = threadIdx.x;            // 0..63
    const int b = t >> 2, q = t & 3;

    // h[b][r] = relu( sum_c pooled[b][c] * w1[r][c] )
    float s = 0.f;
    for (int c = 0; c < NC; c++) s += g_pooled[b*NC + c] * w1[q*NC + c];
    hs[t] = fmaxf(s, 0.f);
    __syncthreads();

    // logits[b][e] = sum_r h[b][r] * w2[e][r]
    float lg = 0.f;
    #pragma unroll
    for (int r = 0; r < NR; r++) lg += hs[b*NR + r] * w2[q*NR + r];
    ls[t] = lg;
    __syncthreads();

    if (t < NB) {
        float m = ls[t*4];
        #pragma unroll
        for (int e = 1; e < NE; e++) m = fmaxf(m, ls[t*4 + e]);
        float ex[NE]; float sum = 0.f;
        #pragma unroll
        for (int e = 0; e < NE; e++) { ex[e] = __expf(ls[t*4 + e] - m); sum += ex[e]; }
        float inv = 1.f / sum;
        #pragma unroll
        for (int e = 0; e < NE; e++) g_attn[t*NE + e] = ex[e] * inv;
    }
    // BN constants, c = t
    float iv = gamma[t] * rsqrtf(var[t] + BN_EPS);
    g_scale[t] = iv;
    g_shift[t] = beta[t] - mean[t] * iv;
}

// ---------------- 3) combine expert weights per batch, transpose to [b][c1][kk][c2] ----------------
// grid: 1024 blocks (b*64+c2), 576 threads (c1*9+kk) -> coalesced expert_w reads
__global__ void comb_k(const float* __restrict__ ew) {   // [E][C2][C1][3][3]
    const int bx = blockIdx.x;
    const int c2 = bx & 63;
    const int b  = bx >> 6;
    const int t  = threadIdx.x;           // 0..575 = c1*9+kk
    float a0 = g_attn[b*NE + 0], a1 = g_attn[b*NE + 1];
    float a2 = g_attn[b*NE + 2], a3 = g_attn[b*NE + 3];
    const int base = c2 * 576;            // (c2)*C1*9
    float s = a0 * ew[0*NC*576 + base + t]
            + a1 * ew[1*NC*576 + base + t]
            + a2 * ew[2*NC*576 + base + t]
            + a3 * ew[3*NC*576 + base + t];
    const int c1 = t / 9, kk = t % 9;
    g_wcomb[(((size_t)b*NC + c1)*9 + kk)*NC + c2] = s;
}

// ---------------- 4) fused conv3x3 + BN + SiLU ----------------
// block: 256 thr = (wt:4) x (ht:8) x (c2t:8); tile: 8h x 32w x 64c2, one batch
// per thread: 8 c2 x 8 w-pixels, accumulated as packed f32x2 pairs
__global__ void __launch_bounds__(256, 2) conv_k(const float* __restrict__ x,
                                                 float* __restrict__ out) {
    const int b  = blockIdx.z;
    const int h0 = blockIdx.y * 8;
    const int w0 = blockIdx.x * 32;

    __shared__ float xs[8][10][35];      // 8 c1 x 10 rows x 34 cols (+pad) = 11.2 KB
    __shared__ float ws[8*9*NC];         // 8 c1 x 9 kk x 64 c2          = 18.4 KB

    const int tid = threadIdx.x;
    const int wt  = tid & 3;
    const int ht  = (tid >> 2) & 7;
    const int c2t = tid >> 5;

    unsigned long long acc[8][4];        // [c2 j][pixel-pair p4], each = 2 x f32
    #pragma unroll
    for (int j = 0; j < 8; j++)
        #pragma unroll
        for (int p = 0; p < 4; p++) acc[j][p] = 0ULL;

    const float* xb = x + (size_t)b * NC * HW;
    const float* wb = g_wcomb + (size_t)b * NC * 9 * NC;

    for (int c1c = 0; c1c < NC; c1c += 8) {
        __syncthreads();
        // weights: contiguous 4608 floats
        for (int i = tid; i < 8*9*NC; i += 256) ws[i] = wb[c1c*9*NC + i];
        // x tile: 8 c1 x 10 rows x 34 cols = 2720, zero-padded halo
        #pragma unroll
        for (int k = 0; k < 11; k++) {
            int i = tid + k*256;
            if (i < 2720) {
                int cc  = i % 34;
                int r   = (i / 34) % 10;
                int c1i = i / 340;
                int gh = h0 + r - 1;
                int gw = w0 + cc - 1;
                float v = 0.f;
                if ((unsigned)gh < (unsigned)NH && (unsigned)gw < (unsigned)NW)
                    v = xb[(c1c + c1i)*HW + gh*NW + gw];
                xs[c1i][r][cc] = v;
            }
        }
        __syncthreads();

        #pragma unroll 2
        for (int c1i = 0; c1i < 8; c1i++) {
            #pragma unroll
            for (int kh = 0; kh < 3; kh++) {
                float xv[10];
                #pragma unroll
                for (int i = 0; i < 10; i++) xv[i] = xs[c1i][ht + kh][wt*8 + i];
                #pragma unroll
                for (int kw = 0; kw < 3; kw++) {
                    unsigned long long xp[4];
                    #pragma unroll
                    for (int p = 0; p < 4; p++)
                        asm("mov.b64 %0, {%1, %2};"
                            : "=l"(xp[p]) : "f"(xv[2*p + kw]), "f"(xv[2*p + kw + 1]));
                    const float* wrow = &ws[((c1i*3 + kh)*3 + kw)*NC + c2t*8];
                    #pragma unroll
                    for (int j = 0; j < 8; j++) {
                        float wv = wrow[j];                 // warp-uniform broadcast LDS
                        unsigned long long wp;
                        asm("mov.b64 %0, {%1, %1};" : "=l"(wp) : "f"(wv));
                        #pragma unroll
                        for (int p = 0; p < 4; p++)
                            asm("fma.rn.f32x2 %0, %1, %2, %0;"
                                : "+l"(acc[j][p]) : "l"(xp[p]), "l"(wp));
                    }
                }
            }
        }
    }

    // epilogue: BN + SiLU, vectorized stores
    const int h = h0 + ht;
    const int wbase = w0 + wt*8;
    #pragma unroll
    for (int j = 0; j < 8; j++) {
        const int c2 = c2t*8 + j;
        const float sc = g_scale[c2];
        const float sh = g_shift[c2];
        float o[8];
        #pragma unroll
        for (int p = 0; p < 4; p++) {
            float lo, hi;
            asm("mov.b64 {%0, %1}, %2;" : "=f"(lo), "=f"(hi) : "l"(acc[j][p]));
            o[2*p] = lo; o[2*p + 1] = hi;
        }
        #pragma unroll
        for (int p = 0; p < 8; p++) {
            float t = o[p]*sc + sh;
            o[p] = t / (1.f + __expf(-t));          // silu
        }
        float4* op = (float4*)(out + (((size_t)(b*NC + c2))*NH + h)*NW + wbase);
        op[0] = make_float4(o[0], o[1], o[2], o[3]);
        op[1] = make_float4(o[4], o[5], o[6], o[7]);
    }
}

// ---------------- launch ----------------
extern "C" void kernel_launch(void* const* d_in, const int* in_sizes, int n_in,
                              void* d_out, int out_size) {
    const float* x     = (const float*)d_in[0];   // [16,64,160,160]
    const float* ew    = (const float*)d_in[1];   // [4,64,64,3,3]
    const float* w1    = (const float*)d_in[2];   // [4,64,1,1]
    const float* w2    = (const float*)d_in[3];   // [4,4,1,1]
    const float* gamma = (const float*)d_in[4];
    const float* beta  = (const float*)d_in[5];
    const float* mean  = (const float*)d_in[6];
    const float* var   = (const float*)d_in[7];
    float* out = (float*)d_out;

    pool_k<<<NB*NC, 256>>>(x);
    attn_k<<<1, 64>>>(w1, w2, gamma, beta, mean, var);
    comb_k<<<NB*NC, 576>>>(ew);
    conv_k<<<dim3(NW/32, NH/8, NB), 256>>>(x, out);
}

// round 2
// speedup vs baseline: 1.1452x; 1.1452x over previous
#include <cuda_runtime.h>
#include <cuda_bf16.h>
#include <cstdint>

// Problem constants: B=16, C1=C2=64, H=W=160, E=4, K=3, R=4
#define NB   16
#define NC   64
#define NH   160
#define NW   160
#define NE   4
#define NR   4
#define HW   (NH*NW)          // 25600
#define BN_EPS 1e-5f

// ---------------- device scratch (no allocations allowed) ----------------
__device__ float g_pooled[NB*NC];            // [b][c]
__device__ float g_attn[NB*NE];              // [b][e]
__device__ float g_scale[NC];                // BN scale
__device__ float g_shift[NC];                // BN shift
__device__ float g_wcomb[NB*NC*9*NC];        // [b][c1][kk][c2]  (2.36 MB)

// ---------------- 1) global average pool ----------------
__global__ void pool_k(const float* __restrict__ x) {
    const int bc = blockIdx.x;                       // 0..1023
    const float4* p4 = (const float4*)(x + (size_t)bc * HW);
    float s = 0.f;
    for (int i = threadIdx.x; i < HW/4; i += 256) {  // 25 iters
        float4 v = p4[i];
        s += (v.x + v.y) + (v.z + v.w);
    }
    #pragma unroll
    for (int o = 16; o > 0; o >>= 1) s += __shfl_down_sync(~0u, s, o);
    __shared__ float sm[8];
    if ((threadIdx.x & 31) == 0) sm[threadIdx.x >> 5] = s;
    __syncthreads();
    if (threadIdx.x < 8) {
        float v = sm[threadIdx.x];
        v += __shfl_down_sync(0xffu, v, 4);
        v += __shfl_down_sync(0xffu, v, 2);
        v += __shfl_down_sync(0xffu, v, 1);
        if (threadIdx.x == 0) g_pooled[bc] = v * (1.f / (float)HW);
    }
}

// ---------------- 2) attention MLP + softmax + BN constants ----------------
__global__ void attn_k(const float* __restrict__ w1,   // [R][C1]
                       const float* __restrict__ w2,   // [E][R]
                       const float* __restrict__ gamma,
                       const float* __restrict__ beta,
                       const float* __restrict__ mean,
                       const float* __restrict__ var) {
    __shared__ float hs[NB*NR];
    __shared__ float ls[NB*NE];
    const int t = threadIdx.x;            // 0..63
    const int b = t >> 2, q = t & 3;

    float s = 0.f;
    for (int c = 0; c < NC; c++) s += g_pooled[b*NC + c] * w1[q*NC + c];
    hs[t] = fmaxf(s, 0.f);
    __syncthreads();

    float lg = 0.f;
    #pragma unroll
    for (int r = 0; r < NR; r++) lg += hs[b*NR + r] * w2[q*NR + r];
    ls[t] = lg;
    __syncthreads();

    if (t < NB) {
        float m = ls[t*4];
        #pragma unroll
        for (int e = 1; e < NE; e++) m = fmaxf(m, ls[t*4 + e]);
        float ex[NE]; float sum = 0.f;
        #pragma unroll
        for (int e = 0; e < NE; e++) { ex[e] = __expf(ls[t*4 + e] - m); sum += ex[e]; }
        float inv = 1.f / sum;
        #pragma unroll
        for (int e = 0; e < NE; e++) g_attn[t*NE + e] = ex[e] * inv;
    }
    float iv = gamma[t] * rsqrtf(var[t] + BN_EPS);
    g_scale[t] = iv;
    g_shift[t] = beta[t] - mean[t] * iv;
}

// ---------------- 3) combine expert weights per batch -> [b][c1][kk][c2] ----------------
__global__ void comb_k(const float* __restrict__ ew) {   // [E][C2][C1][3][3]
    const int bx = blockIdx.x;
    const int c2 = bx & 63;
    const int b  = bx >> 6;
    const int t  = threadIdx.x;           // 0..575 = c1*9+kk
    float a0 = g_attn[b*NE + 0], a1 = g_attn[b*NE + 1];
    float a2 = g_attn[b*NE + 2], a3 = g_attn[b*NE + 3];
    const int base = c2 * 576;
    float s = a0 * ew[0*NC*576 + base + t]
            + a1 * ew[1*NC*576 + base + t]
            + a2 * ew[2*NC*576 + base + t]
            + a3 * ew[3*NC*576 + base + t];
    const int c1 = t / 9, kk = t % 9;
    g_wcomb[(((size_t)b*NC + c1)*9 + kk)*NC + c2] = s;
}

// ---------------- 4) fused conv3x3 + BN + SiLU ----------------
// block: 256 thr: ht = tid[0:3) (8), wt = tid[3:5) (4), c2t = tid[5:8) (8)
// tile: 8h x 32w x 64c2, one batch.  Per thread: 8 pixels x 8 c2.
// acc[p][j]: packed f32x2 over c2 pair (c2t*8+2j, +1), pixel p.
// x in smem pre-duplicated {v,v} -> direct LDS.64 broadcast-pair (no movs).
// weight pairs are contiguous in ws -> warp-uniform LDS.64 (no movs).
__global__ void __launch_bounds__(256, 2) conv_k(const float* __restrict__ x,
                                                 float* __restrict__ out) {
    const int b  = blockIdx.z;
    const int h0 = blockIdx.y * 8;
    const int w0 = blockIdx.x * 32;

    __shared__ float2 xs2[8][10][35];    // 8 c1 x 10 rows x 34 cols {v,v} (+pad) = 22.4 KB
    __shared__ float  ws[8*9*NC];        // 8 c1 x 9 kk x 64 c2 = 18.4 KB

    const int tid = threadIdx.x;
    const int ht  = tid & 7;             // bits 0-2: conflict-free LDS.64 mapping
    const int wt  = (tid >> 3) & 3;      // bits 3-4
    const int c2t = tid >> 5;

    unsigned long long acc[8][4];        // [pixel p][c2-pair j]
    #pragma unroll
    for (int p = 0; p < 8; p++)
        #pragma unroll
        for (int j = 0; j < 4; j++) acc[p][j] = 0ULL;

    const float* xb = x + (size_t)b * NC * HW;
    const float* wb = g_wcomb + (size_t)b * NC * 9 * NC;

    for (int c1c = 0; c1c < NC; c1c += 8) {
        __syncthreads();
        // weights: contiguous 4608 floats
        for (int i = tid; i < 8*9*NC; i += 256) ws[i] = wb[c1c*9*NC + i];
        // x tile: 8 c1 x 10 rows x 34 cols, duplicated {v,v}, zero halo
        #pragma unroll
        for (int k = 0; k < 11; k++) {
            int i = tid + k*256;
            if (i < 2720) {
                int cc  = i % 34;
                int r   = (i / 34) % 10;
                int c1i = i / 340;
                int gh = h0 + r - 1;
                int gw = w0 + cc - 1;
                float v = 0.f;
                if ((unsigned)gh < (unsigned)NH && (unsigned)gw < (unsigned)NW)
                    v = xb[(c1c + c1i)*HW + gh*NW + gw];
                xs2[c1i][r][cc] = make_float2(v, v);
            }
        }
        __syncthreads();

        #pragma unroll 2
        for (int c1i = 0; c1i < 8; c1i++) {
            #pragma unroll
            for (int kh = 0; kh < 3; kh++) {
                // 10 broadcast-pairs {v,v}: direct LDS.64, conflict-free
                const unsigned long long* xrow =
                    (const unsigned long long*)&xs2[c1i][ht + kh][wt*8];
                unsigned long long xq[10];
                #pragma unroll
                for (int q = 0; q < 10; q++) xq[q] = xrow[q];
                #pragma unroll
                for (int kw = 0; kw < 3; kw++) {
                    // 4 weight pairs: warp-uniform LDS.64 (contiguous c2 pair)
                    const unsigned long long* wrow =
                        (const unsigned long long*)&ws[((c1i*3 + kh)*3 + kw)*NC + c2t*8];
                    unsigned long long wp[4];
                    #pragma unroll
                    for (int j = 0; j < 4; j++) wp[j] = wrow[j];
                    #pragma unroll
                    for (int p = 0; p < 8; p++)
                        #pragma unroll
                        for (int j = 0; j < 4; j++)
                            asm("fma.rn.f32x2 %0, %1, %2, %0;"
                                : "+l"(acc[p][j]) : "l"(xq[p + kw]), "l"(wp[j]));
                }
            }
        }
    }

    // epilogue: BN + SiLU, vectorized stores
    const int h = h0 + ht;
    const int wbase = w0 + wt*8;
    #pragma unroll
    for (int j = 0; j < 4; j++) {
        float o0[8], o1[8];                      // c2 = c2t*8+2j, c2t*8+2j+1
        #pragma unroll
        for (int p = 0; p < 8; p++) {
            float lo, hi;
            asm("mov.b64 {%0, %1}, %2;" : "=f"(lo), "=f"(hi) : "l"(acc[p][j]));
            o0[p] = lo; o1[p] = hi;
        }
        const int c2a = c2t*8 + 2*j;
        const float sca = g_scale[c2a],   sha = g_shift[c2a];
        const float scb = g_scale[c2a+1], shb = g_shift[c2a+1];
        #pragma unroll
        for (int p = 0; p < 8; p++) {
            float ta = o0[p]*sca + sha;
            o0[p] = ta / (1.f + __expf(-ta));
            float tb = o1[p]*scb + shb;
            o1[p] = tb / (1.f + __expf(-tb));
        }
        float4* opa = (float4*)(out + (((size_t)(b*NC + c2a))*NH + h)*NW + wbase);
        opa[0] = make_float4(o0[0], o0[1], o0[2], o0[3]);
        opa[1] = make_float4(o0[4], o0[5], o0[6], o0[7]);
        float4* opb = (float4*)(out + (((size_t)(b*NC + c2a + 1))*NH + h)*NW + wbase);
        opb[0] = make_float4(o1[0], o1[1], o1[2], o1[3]);
        opb[1] = make_float4(o1[4], o1[5], o1[6], o1[7]);
    }
}

// ---------------- launch ----------------
extern "C" void kernel_launch(void* const* d_in, const int* in_sizes, int n_in,
                              void* d_out, int out_size) {
    const float* x     = (const float*)d_in[0];   // [16,64,160,160]
    const float* ew    = (const float*)d_in[1];   // [4,64,64,3,3]
    const float* w1    = (const float*)d_in[2];   // [4,64,1,1]
    const float* w2    = (const float*)d_in[3];   // [4,4,1,1]
    const float* gamma = (const float*)d_in[4];
    const float* beta  = (const float*)d_in[5];
    const float* mean  = (const float*)d_in[6];
    const float* var   = (const float*)d_in[7];
    float* out = (float*)d_out;

    pool_k<<<NB*NC, 256>>>(x);
    attn_k<<<1, 64>>>(w1, w2, gamma, beta, mean, var);
    comb_k<<<NB*NC, 576>>>(ew);
    conv_k<<<dim3(NW/32, NH/8, NB), 256>>>(x, out);
}

// round 4
// speedup vs baseline: 1.6948x; 1.4799x over previous
#include <cuda_runtime.h>
#include <cstdint>

// Problem constants: B=16, C1=C2=64, H=W=160, E=4, K=3, R=4
#define NB   16
#define NC   64
#define NH   160
#define NW   160
#define NE   4
#define HW   (NH*NW)          // 25600
#define BN_EPS 1e-5f

// ---------------- device scratch ----------------
__device__ float g_pooled[NB*NC];
__device__ float g_attn[NB*NE];
__device__ float g_scale[NC];
__device__ float g_shift[NC];
// combined weights, tf32 hi / fp32 lo residual, layout [b][kh][kw][c1][c2]
__device__ float g_whi[(size_t)NB*9*NC*NC];
__device__ float g_wlo[(size_t)NB*9*NC*NC];

// ---------------- 1) global average pool ----------------
__global__ void pool_k(const float* __restrict__ x) {
    const int bc = blockIdx.x;
    const float4* p4 = (const float4*)(x + (size_t)bc * HW);
    float s = 0.f;
    for (int i = threadIdx.x; i < HW/4; i += 256) {
        float4 v = p4[i];
        s += (v.x + v.y) + (v.z + v.w);
    }
    #pragma unroll
    for (int o = 16; o > 0; o >>= 1) s += __shfl_down_sync(~0u, s, o);
    __shared__ float sm[8];
    if ((threadIdx.x & 31) == 0) sm[threadIdx.x >> 5] = s;
    __syncthreads();
    if (threadIdx.x < 8) {
        float v = sm[threadIdx.x];
        v += __shfl_down_sync(0xffu, v, 4);
        v += __shfl_down_sync(0xffu, v, 2);
        v += __shfl_down_sync(0xffu, v, 1);
        if (threadIdx.x == 0) g_pooled[bc] = v * (1.f / (float)HW);
    }
}

// ---------------- 2) attention MLP + softmax + BN constants ----------------
__global__ void attn_k(const float* __restrict__ w1, const float* __restrict__ w2,
                       const float* __restrict__ gamma, const float* __restrict__ beta,
                       const float* __restrict__ mean, const float* __restrict__ var) {
    __shared__ float hs[NB*4];
    __shared__ float ls[NB*4];
    const int t = threadIdx.x;            // 0..63
    const int b = t >> 2, q = t & 3;

    float s = 0.f;
    for (int c = 0; c < NC; c++) s += g_pooled[b*NC + c] * w1[q*NC + c];
    hs[t] = fmaxf(s, 0.f);
    __syncthreads();

    float lg = 0.f;
    #pragma unroll
    for (int r = 0; r < 4; r++) lg += hs[b*4 + r] * w2[q*4 + r];
    ls[t] = lg;
    __syncthreads();

    if (t < NB) {
        float m = ls[t*4];
        #pragma unroll
        for (int e = 1; e < NE; e++) m = fmaxf(m, ls[t*4 + e]);
        float ex[NE]; float sum = 0.f;
        #pragma unroll
        for (int e = 0; e < NE; e++) { ex[e] = __expf(ls[t*4 + e] - m); sum += ex[e]; }
        float inv = 1.f / sum;
        #pragma unroll
        for (int e = 0; e < NE; e++) g_attn[t*NE + e] = ex[e] * inv;
    }
    float iv = gamma[t] * rsqrtf(var[t] + BN_EPS);
    g_scale[t] = iv;
    g_shift[t] = beta[t] - mean[t] * iv;
}

// ---------------- 3) combine experts + tf32 hi/lo split ----------------
// out layout: [b][kh][kw][c1][c2]
__global__ void comb_k(const float* __restrict__ ew) {   // [E][C2][C1][3][3]
    const int bx = blockIdx.x;
    const int c2 = bx & 63;
    const int b  = bx >> 6;
    const int t  = threadIdx.x;           // 0..575 = c1*9+kk
    float a0 = g_attn[b*NE + 0], a1 = g_attn[b*NE + 1];
    float a2 = g_attn[b*NE + 2], a3 = g_attn[b*NE + 3];
    const int base = c2 * 576;
    float s = a0 * ew[0*NC*576 + base + t]
            + a1 * ew[1*NC*576 + base + t]
            + a2 * ew[2*NC*576 + base + t]
            + a3 * ew[3*NC*576 + base + t];
    const int c1 = t / 9, kk = t % 9;     // kk = kh*3+kw
    uint32_t hib;
    asm("cvt.rna.tf32.f32 %0, %1;" : "=r"(hib) : "f"(s));
    float hi = __uint_as_float(hib);
    float lo = s - hi;
    size_t o = (((size_t)b*9 + kk)*NC + c1)*NC + c2;
    g_whi[o] = hi;
    g_wlo[o] = lo;
}

// ---------------- 4) tf32 mma.sync implicit-GEMM conv + BN + SiLU ----------------
// CTA: 8h x 32w x 64c2 (M=256, N=64, K=576). 512 thr, warp grid 8(M) x 2(N).
// smem: xs[64 c1][10 r][36 c] (tf32-rounded, zero halo)  = 92160 B
//       wh/wl[3 kw][64 c1][72 c2-pad]                     = 2 x 55296 B
#define XS_SZ (64*10*36)
#define WS_SZ (3*64*72)
#define SMEM_DYN ((XS_SZ + 2*WS_SZ)*4)    // 202752

__device__ __forceinline__ void mma_tf32(float* d, const uint32_t* a, const uint32_t* bq) {
    asm volatile(
        "mma.sync.aligned.m16n8k8.row.col.f32.tf32.tf32.f32 "
        "{%0,%1,%2,%3}, {%4,%5,%6,%7}, {%8,%9}, {%0,%1,%2,%3};"
        : "+f"(d[0]), "+f"(d[1]), "+f"(d[2]), "+f"(d[3])
        : "r"(a[0]), "r"(a[1]), "r"(a[2]), "r"(a[3]), "r"(bq[0]), "r"(bq[1]));
}

__global__ void __launch_bounds__(512, 1) mma_conv_k(const float* __restrict__ x,
                                                     float* __restrict__ out) {
    extern __shared__ float smem[];
    float* xs = smem;                 // [c1][r][c] stride 360/36
    float* wh = smem + XS_SZ;         // [(kw*64+c1)][72]
    float* wl = wh + WS_SZ;

    const int tid  = threadIdx.x;
    const int wid  = tid >> 5;
    const int lane = tid & 31;
    const int wm   = wid >> 1;        // h row within tile (0..7)
    const int wn   = wid & 1;         // c2 half (0..1)
    const int lg   = lane >> 2;       // group id 0..7
    const int lt   = lane & 3;        // thread-in-group

    const int bx = blockIdx.x;        // 1600 = 16 b x 20 ht x 5 wt
    const int b  = bx / 100;
    const int r0 = bx % 100;
    const int h0 = (r0 / 5) * 8;
    const int w0 = (r0 % 5) * 32;

    // ---- stage x tile: 64 c1 x 10 r x 36 c, tf32-rounded, zero halo ----
    const float* xb = x + (size_t)b * NC * HW;
    for (int i = tid; i < XS_SZ; i += 512) {
        const int c1 = i / 360;
        const int r  = (i / 36) % 10;
        const int c  = i % 36;
        const int gh = h0 + r - 1;
        const int gw = w0 + c - 1;
        float v = 0.f;
        if ((unsigned)gh < (unsigned)NH && (unsigned)gw < (unsigned)NW && c < 34)
            v = xb[(size_t)c1*HW + gh*NW + gw];
        uint32_t tv;
        asm("cvt.rna.tf32.f32 %0, %1;" : "=r"(tv) : "f"(v));
        xs[i] = __uint_as_float(tv);
    }

    float d[2][4][4];
    #pragma unroll
    for (int mi = 0; mi < 2; mi++)
        #pragma unroll
        for (int nf = 0; nf < 4; nf++)
            #pragma unroll
            for (int q = 0; q < 4; q++) d[mi][nf][q] = 0.f;

    for (int kh = 0; kh < 3; kh++) {
        __syncthreads();
        // ---- stage weights for this kh: [3 kw][64 c1][64 c2] -> pad 72 ----
        {
            const float4* sh = (const float4*)(g_whi + (((size_t)b*9 + kh*3)*NC)*NC);
            const float4* sl = (const float4*)(g_wlo + (((size_t)b*9 + kh*3)*NC)*NC);
            #pragma unroll
            for (int it = 0; it < 6; it++) {
                const int i   = tid + it*512;        // < 3072 float4
                const int row = i >> 4;              // kw*64 + c1
                const int q4  = i & 15;
                *(float4*)&wh[row*72 + q4*4] = sh[i];
                *(float4*)&wl[row*72 + q4*4] = sl[i];
            }
        }
        __syncthreads();

        const int ar = wm + kh;                       // xs row index
        #pragma unroll
        for (int kw = 0; kw < 3; kw++) {
            #pragma unroll
            for (int oct = 0; oct < 8; oct++) {
                // A fragments (shared by both passes)
                const float* ap = xs + (oct*8 + lt)*360 + ar*36 + lg + kw;
                uint32_t a[2][4];
                #pragma unroll
                for (int mi = 0; mi < 2; mi++) {
                    a[mi][0] = __float_as_uint(ap[mi*16]);
                    a[mi][1] = __float_as_uint(ap[mi*16 + 8]);
                    a[mi][2] = __float_as_uint(ap[mi*16 + 1440]);   // c1+4
                    a[mi][3] = __float_as_uint(ap[mi*16 + 1448]);
                }
                // B fragments hi & lo
                const int boff = (kw*64 + oct*8 + lt)*72 + wn*32 + lg;
                uint32_t bh[4][2], bl[4][2];
                #pragma unroll
                for (int nf = 0; nf < 4; nf++) {
                    bh[nf][0] = __float_as_uint(wh[boff + nf*8]);
                    bh[nf][1] = __float_as_uint(wh[boff + nf*8 + 288]);  // c1+4
                    bl[nf][0] = __float_as_uint(wl[boff + nf*8]);
                    bl[nf][1] = __float_as_uint(wl[boff + nf*8 + 288]);
                }
                #pragma unroll
                for (int mi = 0; mi < 2; mi++)
                    #pragma unroll
                    for (int nf = 0; nf < 4; nf++) {
                        mma_tf32(d[mi][nf], a[mi], bh[nf]);
                        mma_tf32(d[mi][nf], a[mi], bl[nf]);
                    }
            }
        }
    }

    // ---- epilogue: BN + SiLU ----
    const int h = h0 + wm;
    #pragma unroll
    for (int nf = 0; nf < 4; nf++) {
        const int c2 = wn*32 + nf*8 + 2*lt;
        const float s0 = g_scale[c2],   t0 = g_shift[c2];
        const float s1 = g_scale[c2+1], t1 = g_shift[c2+1];
        #pragma unroll
        for (int mi = 0; mi < 2; mi++) {
            const int w = w0 + mi*16 + lg;
            float* o0 = out + ((size_t)(b*NC + c2))*HW + h*NW + w;
            float* o1 = o0 + HW;
            float v;
            v = d[mi][nf][0]*s0 + t0;  o0[0] = v / (1.f + __expf(-v));
            v = d[mi][nf][1]*s1 + t1;  o1[0] = v / (1.f + __expf(-v));
            v = d[mi][nf][2]*s0 + t0;  o0[8] = v / (1.f + __expf(-v));
            v = d[mi][nf][3]*s1 + t1;  o1[8] = v / (1.f + __expf(-v));
        }
    }
}

// ---------------- launch ----------------
extern "C" void kernel_launch(void* const* d_in, const int* in_sizes, int n_in,
                              void* d_out, int out_size) {
    const float* x     = (const float*)d_in[0];   // [16,64,160,160]
    const float* ew    = (const float*)d_in[1];   // [4,64,64,3,3]
    const float* w1    = (const float*)d_in[2];   // [4,64,1,1]
    const float* w2    = (const float*)d_in[3];   // [4,4,1,1]
    const float* gamma = (const float*)d_in[4];
    const float* beta  = (const float*)d_in[5];
    const float* mean  = (const float*)d_in[6];
    const float* var   = (const float*)d_in[7];
    float* out = (float*)d_out;

    static int cfg_done = 0;
    if (!cfg_done) {
        cudaFuncSetAttribute(mma_conv_k, cudaFuncAttributeMaxDynamicSharedMemorySize, SMEM_DYN);
        cfg_done = 1;
    }

    pool_k<<<NB*NC, 256>>>(x);
    attn_k<<<1, 64>>>(w1, w2, gamma, beta, mean, var);
    comb_k<<<NB*NC, 576>>>(ew);
    mma_conv_k<<<16*20*5, 512, SMEM_DYN>>>(x, out);
}